// round 1
// baseline (speedup 1.0000x reference)
#include <cuda_runtime.h>

#define B_SZ   32
#define RESN   100
#define ITERS  1000

// -------- scratch (device globals; no allocation allowed) ----------
__device__ float g_h1[B_SZ * 128];
__device__ float g_h2[B_SZ * 256];
__device__ float g_h3[B_SZ * 512];

// -------------------- MLP layers 1..3 (small) ----------------------
__global__ void fc1_kernel(const float* __restrict__ pores,
                           const float* __restrict__ W,
                           const float* __restrict__ bias) {
    int idx = blockIdx.x * blockDim.x + threadIdx.x;
    if (idx >= B_SZ * 128) return;
    int b = idx >> 7, j = idx & 127;
    float acc = bias[j];
#pragma unroll
    for (int k = 0; k < 25; k++)
        acc = fmaf(pores[b * 25 + k], W[k * 128 + j], acc);
    g_h1[idx] = fmaxf(acc, 0.0f);
}

__global__ void fc2_kernel(const float* __restrict__ W,
                           const float* __restrict__ bias) {
    int idx = blockIdx.x * blockDim.x + threadIdx.x;
    if (idx >= B_SZ * 256) return;
    int b = idx >> 8, j = idx & 255;
    float acc = bias[j];
#pragma unroll 8
    for (int k = 0; k < 128; k++)
        acc = fmaf(g_h1[b * 128 + k], W[k * 256 + j], acc);
    g_h2[idx] = fmaxf(acc, 0.0f);
}

__global__ void fc3_kernel(const float* __restrict__ W,
                           const float* __restrict__ bias) {
    int idx = blockIdx.x * blockDim.x + threadIdx.x;
    if (idx >= B_SZ * 512) return;
    int b = idx >> 9, j = idx & 511;
    float acc = bias[j];
#pragma unroll 8
    for (int k = 0; k < 256; k++)
        acc = fmaf(g_h2[b * 256 + k], W[k * 512 + j], acc);
    g_h3[idx] = fmaxf(acc, 0.0f);
}

// --------- layer 4 + residual + clamp -> cond (B,100,100) ----------
// One thread per output column o; h3 staged in SMEM; 32 accumulators (one
// per batch) so W4 is streamed from HBM exactly once, fully coalesced.
__global__ __launch_bounds__(128) void fc4_kernel(
    const float* __restrict__ W,     // [512,10000]
    const float* __restrict__ bias,  // [10000]
    const float* __restrict__ pores, // [32,25]
    float* __restrict__ cond)        // [32,10000]
{
    extern __shared__ float h3s[];   // 32*512 floats = 64 KB
    for (int i = threadIdx.x; i < B_SZ * 512; i += blockDim.x)
        h3s[i] = g_h3[i];
    __syncthreads();

    int o = blockIdx.x * blockDim.x + threadIdx.x;
    if (o >= RESN * RESN) return;

    float acc[B_SZ];
    float bb = bias[o];
#pragma unroll
    for (int q = 0; q < B_SZ; q++) acc[q] = bb;

    for (int k = 0; k < 512; k += 4) {
        float w0 = W[(k + 0) * 10000 + o];
        float w1 = W[(k + 1) * 10000 + o];
        float w2 = W[(k + 2) * 10000 + o];
        float w3 = W[(k + 3) * 10000 + o];
#pragma unroll
        for (int q = 0; q < B_SZ; q++) {
            float4 h = *reinterpret_cast<const float4*>(&h3s[q * 512 + k]);
            acc[q] = fmaf(h.x, w0, acc[q]);
            acc[q] = fmaf(h.y, w1, acc[q]);
            acc[q] = fmaf(h.z, w2, acc[q]);
            acc[q] = fmaf(h.w, w3, acc[q]);
        }
    }

    int i = o / RESN, j = o % RESN;
    int pidx = (i / 20) * 5 + (j / 20);   // coarse 5x5 pore cell
#pragma unroll
    for (int q = 0; q < B_SZ; q++) {
        float base = 1.0f - pores[q * 25 + pidx];
        cond[q * 10000 + o] = fmaxf(acc[q] + base, 0.01f);
    }
}

// ------------------- Jacobi relaxation (the hot loop) --------------------
// One CTA per batch sample. T double-buffered in SMEM (2*40 KB).
// Each of 500 active threads owns one 20-cell row segment:
//   r = tid % 100 (row), s = tid / 100 (segment 0..4), cols [20s, 20s+20).
// Coefficients rX = kX/denom live in registers (80 regs), own-row T values
// live in registers (20 regs) -> per-iter SMEM traffic is only N/S rows
// (float4) + 2 boundary scalars + the float4 stores.
__global__ __launch_bounds__(512, 1) void jacobi_kernel(
    const float* __restrict__ cond,   // [32,10000]
    float* __restrict__ kappa)        // [32]
{
    extern __shared__ float sm[];
    float* Ta = sm;               // 10000
    float* Tb = sm + 10000;       // 10000
    float* partial = sm + 20000;  // 5

    int b = blockIdx.x;
    const float* k = cond + b * 10000;
    int tid = threadIdx.x;
    bool act = tid < 500;
    int r  = tid % 100;
    int s  = tid / 100;
    int c0 = s * 20;

    float rN[20], rS[20], rW[20], rE[20], Tc[20];

    if (act) {
        int rm = (r == 0)  ? 0  : r - 1;
        int rp = (r == 99) ? 99 : r + 1;
#pragma unroll
        for (int j = 0; j < 20; j++) {
            int c  = c0 + j;
            int cm = (c == 0)  ? 0  : c - 1;
            int cp = (c == 99) ? 99 : c + 1;
            float kc = k[r * 100 + c];
            float kn = 0.5f * (kc + k[rm * 100 + c]);
            float ks = 0.5f * (kc + k[rp * 100 + c]);
            float kw = 0.5f * (kc + k[r * 100 + cm]);
            float ke = 0.5f * (kc + k[r * 100 + cp]);
            float inv = 1.0f / (kn + ks + kw + ke + 1e-12f);
            rN[j] = kn * inv; rS[j] = ks * inv;
            rW[j] = kw * inv; rE[j] = ke * inv;
        }
        float tv = 1.0f - (float)r * (1.0f / 99.0f);  // linspace(1,0,100)[r]
#pragma unroll
        for (int j = 0; j < 20; j++) {
            Tc[j] = tv;
            Ta[r * 100 + c0 + j] = tv;
        }
    }
    __syncthreads();

    float* cur = Ta;
    float* nxt = Tb;

    for (int it = 0; it < ITERS; ++it) {
        if (act) {
            // horizontal boundary values of OLD field
            float left   = (c0 == 0)  ? Tc[0]  : cur[r * 100 + c0 - 1];
            float rightb = (c0 == 80) ? Tc[19] : cur[r * 100 + c0 + 20];
            const float4* nrow = reinterpret_cast<const float4*>(cur + (r - 1) * 100 + c0);
            const float4* srow = reinterpret_cast<const float4*>(cur + (r + 1) * 100 + c0);
            float4* orow = reinterpret_cast<float4*>(nxt + r * 100 + c0);

            float prev = left;
#pragma unroll
            for (int m = 0; m < 5; m++) {
                float4 n4 = (r == 0)  ? make_float4(1.f, 1.f, 1.f, 1.f) : nrow[m];
                float4 s4 = (r == 99) ? make_float4(0.f, 0.f, 0.f, 0.f) : srow[m];
                float tn[4] = {n4.x, n4.y, n4.z, n4.w};
                float ts[4] = {s4.x, s4.y, s4.z, s4.w};
                float res[4];
#pragma unroll
                for (int jj = 0; jj < 4; jj++) {
                    int j = 4 * m + jj;
                    float right = (j == 19) ? rightb : Tc[j + 1];
                    float old = Tc[j];
                    float v = fmaf(rN[j], tn[jj],
                              fmaf(rS[j], ts[jj],
                              fmaf(rW[j], prev, rE[j] * right)));
                    Tc[j] = v;
                    res[jj] = v;
                    prev = old;
                }
                orow[m] = make_float4(res[0], res[1], res[2], res[3]);
            }
        }
        __syncthreads();
        float* t = cur; cur = nxt; nxt = t;
    }

    // kappa = mean_j( 2*res*k[0,j]*(1 - T[0,j]) ) = 2 * sum_j k[0,j]*(1-T[0,j])
    if (act && r == 0) {
        float p = 0.0f;
#pragma unroll
        for (int j = 0; j < 20; j++)
            p += k[c0 + j] * (1.0f - Tc[j]);
        partial[s] = p;
    }
    __syncthreads();
    if (tid == 0)
        kappa[b] = 2.0f * (partial[0] + partial[1] + partial[2] + partial[3] + partial[4]);
}

// --------------------------- launcher ------------------------------
extern "C" void kernel_launch(void* const* d_in, const int* in_sizes, int n_in,
                              void* d_out, int out_size) {
    const float* pores = (const float*)d_in[0];
    const float* W1 = (const float*)d_in[1];
    const float* b1 = (const float*)d_in[2];
    const float* W2 = (const float*)d_in[3];
    const float* b2 = (const float*)d_in[4];
    const float* W3 = (const float*)d_in[5];
    const float* b3 = (const float*)d_in[6];
    const float* W4 = (const float*)d_in[7];
    const float* b4 = (const float*)d_in[8];

    float* out   = (float*)d_out;
    float* kappa = out;          // [32]
    float* cond  = out + B_SZ;   // [32,100,100]

    const int SMEM_FC4 = B_SZ * 512 * sizeof(float);       // 64 KB
    const int SMEM_JAC = (2 * 10000 + 8) * sizeof(float);  // ~80 KB
    cudaFuncSetAttribute(fc4_kernel,    cudaFuncAttributeMaxDynamicSharedMemorySize, SMEM_FC4);
    cudaFuncSetAttribute(jacobi_kernel, cudaFuncAttributeMaxDynamicSharedMemorySize, SMEM_JAC);

    fc1_kernel<<<(B_SZ * 128 + 255) / 256, 256>>>(pores, W1, b1);
    fc2_kernel<<<(B_SZ * 256 + 255) / 256, 256>>>(W2, b2);
    fc3_kernel<<<(B_SZ * 512 + 255) / 256, 256>>>(W3, b3);
    fc4_kernel<<<(10000 + 127) / 128, 128, SMEM_FC4>>>(W4, b4, pores, cond);
    jacobi_kernel<<<B_SZ, 512, SMEM_JAC>>>(cond, kappa);
}